// round 1
// baseline (speedup 1.0000x reference)
#include <cuda_runtime.h>
#include <math.h>

// ---------------------------------------------------------------------------
// Shapes (fixed by the problem)
// ---------------------------------------------------------------------------
#define B    32
#define L    65536
#define LOUT 64536          // L - 1000 (slice [500:-500])

// Scratch (device globals; allocation in kernel_launch is forbidden)
__device__ float g_y[(size_t)B * 40 * L];   // motif output (post-softplus)
__device__ float g_s[(size_t)B * 4 * L];    // reduce output
__device__ float g_t[(size_t)B * 4 * L];    // fftconv output
__device__ float g_m[(size_t)B * 40 * L];   // motifact (gated)

// ---------------------------------------------------------------------------
// Kernel 1: motif conv (4->40, K=51, pad 25) + softplus + reduce (40->4, 1x1)
// ---------------------------------------------------------------------------
#define T1   512            // output positions per block
#define TH1  128
#define K1P  52             // 51 padded to mult of 4 (pad taps have w=0)
#define XW1  564            // T1 + K1P + 4 rounding, mult of 4

__global__ __launch_bounds__(TH1)
void motif_kernel(const float* __restrict__ x,
                  const float* __restrict__ wm, const float* __restrict__ bm,
                  const float* __restrict__ wr, const float* __restrict__ br)
{
    __shared__ __align__(16) float swm[4 * K1P * 40];  // [c][k][oc], k padded
    __shared__ float swr[4 * 40];                      // [rc][oc]
    __shared__ float sbm[40];
    __shared__ float sbr[4];
    __shared__ __align__(16) float sx[4 * XW1];

    const int b   = blockIdx.y;
    const int l0  = blockIdx.x * T1;
    const int tid = threadIdx.x;

    // weights -> smem, transposed to [c][k][oc] with k zero-padded to 52
    for (int i = tid; i < 4 * K1P * 40; i += TH1) {
        int c  = i / (K1P * 40);
        int r  = i - c * (K1P * 40);
        int k  = r / 40;
        int oc = r - k * 40;
        swm[i] = (k < 51) ? wm[(oc * 4 + c) * 51 + k] : 0.f;
    }
    for (int i = tid; i < 160; i += TH1) swr[i] = wr[i];
    if (tid < 40) sbm[tid] = bm[tid];
    if (tid < 4)  sbr[tid] = br[tid];

    // x window [l0-25, l0-25+XW1)
    for (int i = tid; i < 4 * XW1; i += TH1) {
        int c   = i / XW1;
        int off = i - c * XW1;
        int g   = l0 - 25 + off;
        sx[i]   = (g >= 0 && g < L) ? x[(b * 4 + c) * L + g] : 0.f;
    }
    __syncthreads();

    const int tp = tid * 4;     // 4 consecutive output positions per thread

    float sacc[4][4];
#pragma unroll
    for (int rc = 0; rc < 4; rc++) {
        float bv = sbr[rc];
#pragma unroll
        for (int j = 0; j < 4; j++) sacc[rc][j] = bv;
    }

    for (int ocg = 0; ocg < 40; ocg += 8) {
        float acc[8][4];
#pragma unroll
        for (int o = 0; o < 8; o++) {
            float bv = sbm[ocg + o];
#pragma unroll
            for (int j = 0; j < 4; j++) acc[o][j] = bv;
        }

#pragma unroll
        for (int c = 0; c < 4; c++) {
            const float* xb = &sx[c * XW1 + tp];
            const float* wb = &swm[c * (K1P * 40) + ocg];
#pragma unroll 1
            for (int kg = 0; kg < K1P / 4; kg++) {
                const int k0 = kg * 4;
                float xq[8];
                float4 xa = *(const float4*)(xb + k0);
                float4 xc = *(const float4*)(xb + k0 + 4);
                xq[0]=xa.x; xq[1]=xa.y; xq[2]=xa.z; xq[3]=xa.w;
                xq[4]=xc.x; xq[5]=xc.y; xq[6]=xc.z; xq[7]=xc.w;
#pragma unroll
                for (int kk = 0; kk < 4; kk++) {
                    float4 wa = *(const float4*)(wb + (k0 + kk) * 40);
                    float4 wc = *(const float4*)(wb + (k0 + kk) * 40 + 4);
                    float wv[8] = {wa.x, wa.y, wa.z, wa.w, wc.x, wc.y, wc.z, wc.w};
#pragma unroll
                    for (int j = 0; j < 4; j++) {
                        float xv = xq[kk + j];
#pragma unroll
                        for (int o = 0; o < 8; o++)
                            acc[o][j] = fmaf(wv[o], xv, acc[o][j]);
                    }
                }
            }
        }

        // softplus, write y, accumulate reduce
#pragma unroll
        for (int o = 0; o < 8; o++) {
            const int oc = ocg + o;
            float4 yv;
            float* yp = (float*)&yv;
#pragma unroll
            for (int j = 0; j < 4; j++) {
                float v  = acc[o][j];
                float sp = fmaxf(v, 0.f) + log1pf(expf(-fabsf(v)));
                yp[j] = sp;
#pragma unroll
                for (int rc = 0; rc < 4; rc++)
                    sacc[rc][j] = fmaf(swr[rc * 40 + oc], sp, sacc[rc][j]);
            }
            *(float4*)&g_y[(size_t)(b * 40 + oc) * L + l0 + tp] = yv;
        }
    }

#pragma unroll
    for (int rc = 0; rc < 4; rc++) {
        float4 sv = make_float4(sacc[rc][0], sacc[rc][1], sacc[rc][2], sacc[rc][3]);
        *(float4*)&g_s[(size_t)(b * 4 + rc) * L + l0 + tp] = sv;
    }
}

// ---------------------------------------------------------------------------
// Kernel 2: fftconv (4->4, K=401, pad 200)
// ---------------------------------------------------------------------------
#define T3   512
#define TH3  128
#define K3P  404            // 401 padded to mult of 4
#define XW3  920            // T3 + K3P + 4, mult of 4

__global__ __launch_bounds__(TH3)
void fftconv_kernel(const float* __restrict__ wf, const float* __restrict__ bf)
{
    __shared__ __align__(16) float sw[4 * K3P * 4];    // [c][k][oc]
    __shared__ float sb[4];
    __shared__ __align__(16) float ss[4 * XW3];

    const int b   = blockIdx.y;
    const int l0  = blockIdx.x * T3;
    const int tid = threadIdx.x;

    for (int i = tid; i < 4 * K3P * 4; i += TH3) {
        int c  = i / (K3P * 4);
        int r  = i - c * (K3P * 4);
        int k  = r / 4;
        int oc = r - k * 4;
        sw[i] = (k < 401) ? wf[(oc * 4 + c) * 401 + k] : 0.f;
    }
    if (tid < 4) sb[tid] = bf[tid];

    for (int i = tid; i < 4 * XW3; i += TH3) {
        int c   = i / XW3;
        int off = i - c * XW3;
        int g   = l0 - 200 + off;
        ss[i]   = (g >= 0 && g < L) ? g_s[(size_t)(b * 4 + c) * L + g] : 0.f;
    }
    __syncthreads();

    const int tp = tid * 4;
    float acc[4][4];
#pragma unroll
    for (int oc = 0; oc < 4; oc++) {
        float bv = sb[oc];
#pragma unroll
        for (int j = 0; j < 4; j++) acc[oc][j] = bv;
    }

#pragma unroll
    for (int c = 0; c < 4; c++) {
        const float* xb = &ss[c * XW3 + tp];
        const float* wb = &sw[c * (K3P * 4)];
#pragma unroll 1
        for (int kg = 0; kg < K3P / 4; kg++) {
            const int k0 = kg * 4;
            float xq[8];
            float4 xa = *(const float4*)(xb + k0);
            float4 xc = *(const float4*)(xb + k0 + 4);
            xq[0]=xa.x; xq[1]=xa.y; xq[2]=xa.z; xq[3]=xa.w;
            xq[4]=xc.x; xq[5]=xc.y; xq[6]=xc.z; xq[7]=xc.w;
#pragma unroll
            for (int kk = 0; kk < 4; kk++) {
                float4 wv = *(const float4*)(wb + (k0 + kk) * 4);
                float w0 = wv.x, w1 = wv.y, w2 = wv.z, w3 = wv.w;
#pragma unroll
                for (int j = 0; j < 4; j++) {
                    float xv = xq[kk + j];
                    acc[0][j] = fmaf(w0, xv, acc[0][j]);
                    acc[1][j] = fmaf(w1, xv, acc[1][j]);
                    acc[2][j] = fmaf(w2, xv, acc[2][j]);
                    acc[3][j] = fmaf(w3, xv, acc[3][j]);
                }
            }
        }
    }

#pragma unroll
    for (int oc = 0; oc < 4; oc++) {
        float4 tv = make_float4(acc[oc][0], acc[oc][1], acc[oc][2], acc[oc][3]);
        *(float4*)&g_t[(size_t)(b * 4 + oc) * L + l0 + tp] = tv;
    }
}

// ---------------------------------------------------------------------------
// Kernel 3: expand (4->40, 1x1) + sigmoid gate * y  -> motifact
// ---------------------------------------------------------------------------
__global__ __launch_bounds__(256)
void gate_kernel(const float* __restrict__ we, const float* __restrict__ be)
{
    __shared__ float sw[160];
    __shared__ float sb[40];
    const int tid = threadIdx.x;
    if (tid < 160) sw[tid] = we[tid];
    if (tid < 40)  sb[tid] = be[tid];
    __syncthreads();

    const int b = blockIdx.y;
    const int l = (blockIdx.x * 256 + tid) * 4;

    float4 tv[4];
#pragma unroll
    for (int rc = 0; rc < 4; rc++)
        tv[rc] = *(const float4*)&g_t[(size_t)(b * 4 + rc) * L + l];

    for (int oc = 0; oc < 40; oc++) {
        float w0 = sw[oc * 4 + 0], w1 = sw[oc * 4 + 1];
        float w2 = sw[oc * 4 + 2], w3 = sw[oc * 4 + 3];
        float bb = sb[oc];
        float4 g;
        g.x = bb + w0 * tv[0].x + w1 * tv[1].x + w2 * tv[2].x + w3 * tv[3].x;
        g.y = bb + w0 * tv[0].y + w1 * tv[1].y + w2 * tv[2].y + w3 * tv[3].y;
        g.z = bb + w0 * tv[0].z + w1 * tv[1].z + w2 * tv[2].z + w3 * tv[3].z;
        g.w = bb + w0 * tv[0].w + w1 * tv[1].w + w2 * tv[2].w + w3 * tv[3].w;
        g.x = 1.f / (1.f + __expf(-g.x));
        g.y = 1.f / (1.f + __expf(-g.y));
        g.z = 1.f / (1.f + __expf(-g.z));
        g.w = 1.f / (1.f + __expf(-g.w));
        size_t idx = (size_t)(b * 40 + oc) * L + l;
        float4 yv = *(const float4*)&g_y[idx];
        float4 mv = make_float4(g.x * yv.x, g.y * yv.y, g.z * yv.z, g.w * yv.w);
        *(float4*)&g_m[idx] = mv;
    }
}

// ---------------------------------------------------------------------------
// Kernel 4: effect conv (40->2, K=601, pad 300) + sigmoid + slice [500:-500]
// ---------------------------------------------------------------------------
#define T5   1024           // output positions per block
#define TH5  128
#define NP5  8              // positions per thread (consecutive)
#define K5P  608            // 601 padded to mult of 8
#define W5   1648           // T5 + K5P + 16, mult of 16
#define CH5  4              // channels per smem chunk

__global__ __launch_bounds__(TH5)
void effect_kernel(const float* __restrict__ w, const float* __restrict__ bias,
                   float* __restrict__ out)
{
    __shared__ __align__(16) float sm[CH5 * W5];        // m window per chunk
    __shared__ __align__(16) float swt[CH5 * K5P * 2];  // [cc][k][o], padded

    const int b   = blockIdx.y;
    const int lo0 = blockIdx.x * T5;        // offset in output coords
    const int g0  = lo0 + 200;              // = (500 + lo0) - 300, always >= 0
    const int tid = threadIdx.x;
    const int tp  = tid * NP5;

    float acc0[NP5], acc1[NP5];
    const float b0 = bias[0], b1 = bias[1];
#pragma unroll
    for (int j = 0; j < NP5; j++) { acc0[j] = b0; acc1[j] = b1; }

    for (int ch0 = 0; ch0 < 40; ch0 += CH5) {
        __syncthreads();   // protect previous chunk's smem until all done
        for (int i = tid; i < CH5 * K5P * 2; i += TH5) {
            int o    = i & 1;
            int rest = i >> 1;
            int k    = rest % K5P;
            int cc   = rest / K5P;
            swt[i] = (k < 601) ? w[((size_t)(o * 40 + ch0 + cc)) * 601 + k] : 0.f;
        }
        for (int i = tid; i < CH5 * W5; i += TH5) {
            int cc  = i / W5;
            int off = i - cc * W5;
            int g   = g0 + off;
            sm[i]   = (g < L) ? g_m[(size_t)(b * 40 + ch0 + cc) * L + g] : 0.f;
        }
        __syncthreads();

        for (int cc = 0; cc < CH5; cc++) {
            const float* xb = &sm[cc * W5 + tp];
            const float* wb = &swt[cc * (K5P * 2)];
#pragma unroll 1
            for (int k0 = 0; k0 < K5P; k0 += 8) {
                float xw[16];
#pragma unroll
                for (int q = 0; q < 4; q++) {
                    float4 v = *(const float4*)(xb + k0 + q * 4);
                    xw[q * 4 + 0] = v.x; xw[q * 4 + 1] = v.y;
                    xw[q * 4 + 2] = v.z; xw[q * 4 + 3] = v.w;
                }
#pragma unroll
                for (int kk = 0; kk < 8; kk++) {
                    float2 w2 = *(const float2*)(wb + (k0 + kk) * 2);
#pragma unroll
                    for (int j = 0; j < NP5; j++) {
                        float xv = xw[kk + j];
                        acc0[j] = fmaf(w2.x, xv, acc0[j]);
                        acc1[j] = fmaf(w2.y, xv, acc1[j]);
                    }
                }
            }
        }
    }

#pragma unroll
    for (int j = 0; j < NP5; j++) {
        int lo = lo0 + tp + j;
        if (lo < LOUT) {
            out[(size_t)(b * 2 + 0) * LOUT + lo] = 1.f / (1.f + expf(-acc0[j]));
            out[(size_t)(b * 2 + 1) * LOUT + lo] = 1.f / (1.f + expf(-acc1[j]));
        }
    }
}

// ---------------------------------------------------------------------------
// Launch
// ---------------------------------------------------------------------------
extern "C" void kernel_launch(void* const* d_in, const int* in_sizes, int n_in,
                              void* d_out, int out_size)
{
    const float* x   = (const float*)d_in[0];
    const float* wm  = (const float*)d_in[1];
    const float* bm  = (const float*)d_in[2];
    const float* wr  = (const float*)d_in[3];
    const float* br  = (const float*)d_in[4];
    const float* wf  = (const float*)d_in[5];
    const float* bf  = (const float*)d_in[6];
    const float* wex = (const float*)d_in[7];
    const float* bex = (const float*)d_in[8];
    const float* wef = (const float*)d_in[9];
    const float* bef = (const float*)d_in[10];
    float* out = (float*)d_out;

    motif_kernel  <<<dim3(L / T1, B), TH1>>>(x, wm, bm, wr, br);
    fftconv_kernel<<<dim3(L / T3, B), TH3>>>(wf, bf);
    gate_kernel   <<<dim3(L / 1024, B), 256>>>(wex, bex);
    effect_kernel <<<dim3((LOUT + T5 - 1) / T5, B), TH5>>>(wef, bef, out);
}